// round 14
// baseline (speedup 1.0000x reference)
#include <cuda_runtime.h>

// Shapes (fixed for this problem)
#define B_  2
#define T_  2048
#define H_  8
#define D_  64
#define M_  64
#define C_  32                 // chunk length (timesteps per block)
#define NC_ (T_ / C_)          // 64 chunks per (b,h)
#define RS  512                // row stride in floats between consecutive t (H*D)

// Per-(b,h,chunk) column sums of fmap(k): [B*H*NC][D]
__device__ float g_chunksum[B_ * H_ * NC_ * D_];

__device__ __forceinline__ float fmap(float x) {
    // elu(x) + 1 (alpha=1): x>0 -> x+1 ; x<=0 -> exp(x)
    return x > 0.0f ? x + 1.0f : __expf(x);
}
__device__ __forceinline__ float4 fmap4(float4 a) {
    return make_float4(fmap(a.x), fmap(a.y), fmap(a.z), fmap(a.w));
}
__device__ __forceinline__ float2 fmap2(float2 a) {
    return make_float2(fmap(a.x), fmap(a.y));
}
__device__ __forceinline__ float4 add4(float4 a, float4 b) {
    return make_float4(a.x + b.x, a.y + b.y, a.z + b.z, a.w + b.w);
}

// ---------------------------------------------------------------------------
// Kernel 1: per-chunk column sums of fmap(k). grid = 1024 blocks, 256 thr.
// ---------------------------------------------------------------------------
__global__ __launch_bounds__(256, 7) void k_chunksum(const float* __restrict__ k) {
    __shared__ float4 red[16][16];          // [tg][dv]
    const int bc  = blockIdx.x;             // bh*64 + c
    const int c   = bc & (NC_ - 1);
    const int bh  = bc >> 6;
    const int h   = bh & (H_ - 1);
    const int b   = bh >> 3;
    const int tid = threadIdx.x;
    const int tg  = tid >> 4;
    const int dv  = tid & 15;

    const size_t base = (((size_t)b * T_ + (size_t)c * C_) * H_ + h) * D_;

    float4 s = make_float4(0.f, 0.f, 0.f, 0.f);
    #pragma unroll
    for (int i = 0; i < 2; i++) {
        const int t = tg + i * 16;
        s = add4(s, fmap4(*(const float4*)(k + base + (size_t)t * RS + dv * 4)));
    }
    red[tg][dv] = s;
    __syncthreads();

    if (tid < 16) {
        float4 acc = red[0][tid];
        #pragma unroll
        for (int t = 1; t < 16; t++) acc = add4(acc, red[t][tid]);
        *(float4*)(&g_chunksum[bc * D_ + tid * 4]) = acc;
    }
}

// ---------------------------------------------------------------------------
// Kernel 2: warp-autonomous main. grid = 1024 blocks x 256 threads (8 warps).
// Warp w owns timesteps {4w..4w+3}; lane l owns d in {2l, 2l+1}. Everything
// in registers; smem only for per-warp column sums + carry partials. ONE
// block-wide barrier.
// ---------------------------------------------------------------------------
__global__ __launch_bounds__(256, 5) void k_main(const float* __restrict__ q,
                                                 const float* __restrict__ k,
                                                 const float* __restrict__ v,
                                                 float* __restrict__ out) {
    __shared__ float2 wsum[8][32];         // per-warp column sums, lane-indexed (d-pair)
    __shared__ float  carp[4 * 64];        // carry partials (4-way split over priors)

    const int bc  = blockIdx.x;
    const int c   = bc & (NC_ - 1);
    const int bh  = bc >> 6;
    const int h   = bh & (H_ - 1);
    const int b   = bh >> 3;
    const int tid = threadIdx.x;
    const int w   = tid >> 5;              // warp: rows 4w..4w+3
    const int l   = tid & 31;              // lane: d-pair {2l, 2l+1}

    const size_t base = (((size_t)b * T_ + (size_t)c * C_) * H_ + h) * D_;
    const size_t row0 = base + (size_t)(4 * w) * RS + 2 * l;

    // ---- all gmem loads issued up front (12 LDG.64s, big MLP) ----
    float2 kr[4], qr[4], vr[4];
    #pragma unroll
    for (int r = 0; r < 4; r++) {
        kr[r] = *(const float2*)(k + row0 + (size_t)r * RS);
        qr[r] = *(const float2*)(q + row0 + (size_t)r * RS);
        vr[r] = *(const float2*)(v + row0 + (size_t)r * RS);
    }

    // ---- carry partials: 4-way chunk split over up to c priors (L2 loads) ----
    {
        const int d = tid & 63, p = tid >> 6;
        const int lo = p * 16;
        const int hi = (c < lo + 16) ? c : (lo + 16);
        float run = 0.0f;
        const float* cs = &g_chunksum[(bh << 6) * D_ + d];
        #pragma unroll 4
        for (int cc = lo; cc < hi; cc++) run += cs[cc * D_];
        carp[p * 64 + d] = run;
    }

    // ---- feature maps + per-warp column sums ----
    float2 kf[4], qf[4];
    float cs0 = 0.0f, cs1 = 0.0f;
    #pragma unroll
    for (int r = 0; r < 4; r++) {
        kf[r] = fmap2(kr[r]);
        qf[r] = fmap2(qr[r]);
        cs0 += kf[r].x;
        cs1 += kf[r].y;
    }
    wsum[w][l] = make_float2(cs0, cs1);
    __syncthreads();                       // the ONLY block barrier

    // ---- per-lane carry (sum of 4 partials, float2 LDS) ----
    float run0, run1;
    {
        const float2* cp = (const float2*)carp;
        const float2 a = cp[l], bb = cp[32 + l], cc2 = cp[64 + l], dd = cp[96 + l];
        run0 = a.x + bb.x + cc2.x + dd.x;
        run1 = a.y + bb.y + cc2.y + dd.y;
    }
    // ---- add prior warps' column sums (warp-uniform loop) ----
    for (int ww = 0; ww < w; ww++) {
        const float2 s = wsum[ww][l];
        run0 += s.x;
        run1 += s.y;
    }

    // ---- per-row: finish time-cumsum in regs; den; in-row d-scan for S ----
    float S[4], den[4];
    #pragma unroll
    for (int r = 0; r < 4; r++) {
        run0 += kf[r].x;
        run1 += kf[r].y;
        den[r] = qf[r].x * run0 + qf[r].y * run1;

        const float pr = kf[r].x + kf[r].y;
        float incl = pr;
        #pragma unroll
        for (int o = 1; o < 32; o <<= 1) {
            const float n = __shfl_up_sync(0xFFFFFFFFu, incl, o);
            if (l >= o) incl += n;
        }
        const float pre = incl - pr;                  // exclusive prefix of pair-sums
        S[r] = qf[r].x * (pre + kf[r].x) + qf[r].y * incl;
    }

    // ---- butterfly reductions (4 independent rows -> ILP) ----
    #pragma unroll
    for (int r = 0; r < 4; r++) {
        #pragma unroll
        for (int o = 16; o > 0; o >>= 1) {
            S[r]   += __shfl_xor_sync(0xFFFFFFFFu, S[r], o);
            den[r] += __shfl_xor_sync(0xFFFFFFFFu, den[r], o);
        }
    }

    // ---- scale and store ----
    #pragma unroll
    for (int r = 0; r < 4; r++) {
        const float sc = S[r] / den[r];
        float2 o2 = vr[r];
        o2.x *= sc;
        o2.y *= sc;
        *(float2*)(out + row0 + (size_t)r * RS) = o2;
    }
}

extern "C" void kernel_launch(void* const* d_in, const int* in_sizes, int n_in,
                              void* d_out, int out_size) {
    const float* q = (const float*)d_in[0];
    const float* k = (const float*)d_in[1];
    const float* v = (const float*)d_in[2];
    float* out = (float*)d_out;

    const int nblocks = B_ * H_ * NC_;     // 1024
    k_chunksum<<<nblocks, 256>>>(k);
    k_main<<<nblocks, 256>>>(q, k, v, out);
}

// round 15
// speedup vs baseline: 1.2565x; 1.2565x over previous
#include <cuda_runtime.h>

// Shapes (fixed for this problem)
#define B_  2
#define T_  2048
#define H_  8
#define D_  64
#define M_  64
#define C_  32                 // chunk length (timesteps per block)
#define NC_ (T_ / C_)          // 64 chunks per (b,h)
#define RS  512                // row stride in floats between consecutive t (H*D)

// Per-(b,h,chunk) column sums of fmap(k): [B*H*NC][D]
__device__ float g_chunksum[B_ * H_ * NC_ * D_];

__device__ __forceinline__ float fmap(float x) {
    // elu(x) + 1 (alpha=1): x>0 -> x+1 ; x<=0 -> exp(x)
    return x > 0.0f ? x + 1.0f : __expf(x);
}
__device__ __forceinline__ float4 fmap4(float4 a) {
    return make_float4(fmap(a.x), fmap(a.y), fmap(a.z), fmap(a.w));
}
__device__ __forceinline__ float2 fmap2(float2 a) {
    return make_float2(fmap(a.x), fmap(a.y));
}
__device__ __forceinline__ float4 add4(float4 a, float4 b) {
    return make_float4(a.x + b.x, a.y + b.y, a.z + b.z, a.w + b.w);
}

// ---------------------------------------------------------------------------
// Kernel 1: per-chunk column sums of fmap(k). grid = 1024, 256 threads.
// EXACT R6/R10 form (plain launch_bounds(256) — the (256,7) variant measured
// ~6us vs ~0.8us for this one).
// ---------------------------------------------------------------------------
__global__ __launch_bounds__(256) void k_chunksum(const float* __restrict__ k) {
    __shared__ float4 red[16][16];          // [tg][dv]
    const int bc  = blockIdx.x;             // bh*64 + c
    const int c   = bc & (NC_ - 1);
    const int bh  = bc >> 6;
    const int h   = bh & (H_ - 1);
    const int b   = bh >> 3;
    const int tid = threadIdx.x;
    const int tg  = tid >> 4;
    const int dv  = tid & 15;

    const size_t base = (((size_t)b * T_ + (size_t)c * C_) * H_ + h) * D_;

    float4 s = make_float4(0.f, 0.f, 0.f, 0.f);
    #pragma unroll
    for (int i = 0; i < 2; i++) {
        const int t = tg + i * 16;
        s = add4(s, fmap4(*(const float4*)(k + base + (size_t)t * RS + dv * 4)));
    }
    red[tg][dv] = s;
    __syncthreads();

    if (tid < 16) {
        float4 acc = red[0][tid];
        #pragma unroll
        for (int t = 1; t < 16; t++) acc = add4(acc, red[t][tid]);
        *(float4*)(&g_chunksum[bc * D_ + tid * 4]) = acc;
    }
}

// ---------------------------------------------------------------------------
// Kernel 2: warp-autonomous main (R14, unchanged — best per-kernel result).
// grid = 1024 blocks x 256 threads (8 warps). Warp w owns timesteps
// {4w..4w+3}; lane l owns d in {2l, 2l+1}. ONE block-wide barrier.
// ---------------------------------------------------------------------------
__global__ __launch_bounds__(256, 5) void k_main(const float* __restrict__ q,
                                                 const float* __restrict__ k,
                                                 const float* __restrict__ v,
                                                 float* __restrict__ out) {
    __shared__ float2 wsum[8][32];         // per-warp column sums, lane-indexed (d-pair)
    __shared__ float  carp[4 * 64];        // carry partials (4-way split over priors)

    const int bc  = blockIdx.x;
    const int c   = bc & (NC_ - 1);
    const int bh  = bc >> 6;
    const int h   = bh & (H_ - 1);
    const int b   = bh >> 3;
    const int tid = threadIdx.x;
    const int w   = tid >> 5;              // warp: rows 4w..4w+3
    const int l   = tid & 31;              // lane: d-pair {2l, 2l+1}

    const size_t base = (((size_t)b * T_ + (size_t)c * C_) * H_ + h) * D_;
    const size_t row0 = base + (size_t)(4 * w) * RS + 2 * l;

    // ---- all gmem loads issued up front (12 LDG.64s, big MLP) ----
    float2 kr[4], qr[4], vr[4];
    #pragma unroll
    for (int r = 0; r < 4; r++) {
        kr[r] = *(const float2*)(k + row0 + (size_t)r * RS);
        qr[r] = *(const float2*)(q + row0 + (size_t)r * RS);
        vr[r] = *(const float2*)(v + row0 + (size_t)r * RS);
    }

    // ---- carry partials: 4-way chunk split over up to c priors (L2 loads) ----
    {
        const int d = tid & 63, p = tid >> 6;
        const int lo = p * 16;
        const int hi = (c < lo + 16) ? c : (lo + 16);
        float run = 0.0f;
        const float* cs = &g_chunksum[(bh << 6) * D_ + d];
        #pragma unroll 4
        for (int cc = lo; cc < hi; cc++) run += cs[cc * D_];
        carp[p * 64 + d] = run;
    }

    // ---- feature maps + per-warp column sums ----
    float2 kf[4], qf[4];
    float cs0 = 0.0f, cs1 = 0.0f;
    #pragma unroll
    for (int r = 0; r < 4; r++) {
        kf[r] = fmap2(kr[r]);
        qf[r] = fmap2(qr[r]);
        cs0 += kf[r].x;
        cs1 += kf[r].y;
    }
    wsum[w][l] = make_float2(cs0, cs1);
    __syncthreads();                       // the ONLY block barrier

    // ---- per-lane carry (sum of 4 partials, float2 LDS) ----
    float run0, run1;
    {
        const float2* cp = (const float2*)carp;
        const float2 a = cp[l], bb = cp[32 + l], cc2 = cp[64 + l], dd = cp[96 + l];
        run0 = a.x + bb.x + cc2.x + dd.x;
        run1 = a.y + bb.y + cc2.y + dd.y;
    }
    // ---- add prior warps' column sums (warp-uniform loop) ----
    for (int ww = 0; ww < w; ww++) {
        const float2 s = wsum[ww][l];
        run0 += s.x;
        run1 += s.y;
    }

    // ---- per-row: finish time-cumsum in regs; den; in-row d-scan for S ----
    float S[4], den[4];
    #pragma unroll
    for (int r = 0; r < 4; r++) {
        run0 += kf[r].x;
        run1 += kf[r].y;
        den[r] = qf[r].x * run0 + qf[r].y * run1;

        const float pr = kf[r].x + kf[r].y;
        float incl = pr;
        #pragma unroll
        for (int o = 1; o < 32; o <<= 1) {
            const float n = __shfl_up_sync(0xFFFFFFFFu, incl, o);
            if (l >= o) incl += n;
        }
        const float pre = incl - pr;                  // exclusive prefix of pair-sums
        S[r] = qf[r].x * (pre + kf[r].x) + qf[r].y * incl;
    }

    // ---- butterfly reductions (4 independent rows -> ILP) ----
    #pragma unroll
    for (int r = 0; r < 4; r++) {
        #pragma unroll
        for (int o = 16; o > 0; o >>= 1) {
            S[r]   += __shfl_xor_sync(0xFFFFFFFFu, S[r], o);
            den[r] += __shfl_xor_sync(0xFFFFFFFFu, den[r], o);
        }
    }

    // ---- scale and store ----
    #pragma unroll
    for (int r = 0; r < 4; r++) {
        const float sc = S[r] / den[r];
        float2 o2 = vr[r];
        o2.x *= sc;
        o2.y *= sc;
        *(float2*)(out + row0 + (size_t)r * RS) = o2;
    }
}

extern "C" void kernel_launch(void* const* d_in, const int* in_sizes, int n_in,
                              void* d_out, int out_size) {
    const float* q = (const float*)d_in[0];
    const float* k = (const float*)d_in[1];
    const float* v = (const float*)d_in[2];
    float* out = (float*)d_out;

    const int nblocks = B_ * H_ * NC_;     // 1024
    k_chunksum<<<nblocks, 256>>>(k);
    k_main<<<nblocks, 256>>>(q, k, v, out);
}

// round 16
// speedup vs baseline: 1.3190x; 1.0498x over previous
#include <cuda_runtime.h>

// Shapes (fixed for this problem)
#define B_  2
#define T_  2048
#define H_  8
#define D_  64
#define M_  64
#define C_  32                 // chunk length (timesteps per block)
#define NC_ (T_ / C_)          // 64 chunks per (b,h)
#define RS  512                // row stride in floats between consecutive t (H*D)

// Per-(b,h,chunk) column sums of fmap(k): [B*H*NC][D]
__device__ float g_chunksum[B_ * H_ * NC_ * D_];

__device__ __forceinline__ float fmap(float x) {
    // elu(x) + 1 (alpha=1): x>0 -> x+1 ; x<=0 -> exp(x)
    return x > 0.0f ? x + 1.0f : __expf(x);
}
__device__ __forceinline__ float4 fmap4(float4 a) {
    return make_float4(fmap(a.x), fmap(a.y), fmap(a.z), fmap(a.w));
}
__device__ __forceinline__ float4 add4(float4 a, float4 b) {
    return make_float4(a.x + b.x, a.y + b.y, a.z + b.z, a.w + b.w);
}
__device__ __forceinline__ float dot4(float4 a, float4 b) {
    return a.x * b.x + a.y * b.y + a.z * b.z + a.w * b.w;
}

// ---------------------------------------------------------------------------
// Kernel 1: per-chunk column sums of fmap(k). grid = 1024, 256 threads.
// (plain launch_bounds(256): the (256,7) variant measured ~6us vs ~0.8us)
// ---------------------------------------------------------------------------
__global__ __launch_bounds__(256) void k_chunksum(const float* __restrict__ k) {
    __shared__ float4 red[16][16];          // [tg][dv]
    const int bc  = blockIdx.x;             // bh*64 + c
    const int c   = bc & (NC_ - 1);
    const int bh  = bc >> 6;
    const int h   = bh & (H_ - 1);
    const int b   = bh >> 3;
    const int tid = threadIdx.x;
    const int tg  = tid >> 4;
    const int dv  = tid & 15;

    const size_t base = (((size_t)b * T_ + (size_t)c * C_) * H_ + h) * D_;

    float4 s = make_float4(0.f, 0.f, 0.f, 0.f);
    #pragma unroll
    for (int i = 0; i < 2; i++) {
        const int t = tg + i * 16;
        s = add4(s, fmap4(*(const float4*)(k + base + (size_t)t * RS + dv * 4)));
    }
    red[tg][dv] = s;
    __syncthreads();

    if (tid < 16) {
        float4 acc = red[0][tid];
        #pragma unroll
        for (int t = 1; t < 16; t++) acc = add4(acc, red[t][tid]);
        *(float4*)(&g_chunksum[bc * D_ + tid * 4]) = acc;
    }
}

// ---------------------------------------------------------------------------
// Kernel 2: warp-autonomous main, half-warp row layout.
// grid = 1024 blocks x 256 threads (8 warps). Warp w owns rows 4w..4w+3:
// lanes 0-15 -> rows {4w, 4w+1}, lanes 16-31 -> rows {4w+2, 4w+3}.
// Each lane owns a float4 d-group (d = 4*l16 .. 4*l16+3) in its two rows.
// All scans/reductions are width-16 (4 steps). ONE block barrier.
// ---------------------------------------------------------------------------
__global__ __launch_bounds__(256, 5) void k_main(const float* __restrict__ q,
                                                 const float* __restrict__ k,
                                                 const float* __restrict__ v,
                                                 float* __restrict__ out) {
    __shared__ float4 wsum[8][16];         // per-warp column sums over its 4 rows
    __shared__ float  carp[4 * 64];        // carry partials (4-way split over priors)

    const int bc  = blockIdx.x;
    const int c   = bc & (NC_ - 1);
    const int bh  = bc >> 6;
    const int h   = bh & (H_ - 1);
    const int b   = bh >> 3;
    const int tid = threadIdx.x;
    const int w   = tid >> 5;              // warp
    const int l   = tid & 31;
    const int h16 = l >> 4;                // half-warp: row pair selector
    const int l16 = l & 15;                // d-group index

    const size_t base = (((size_t)b * T_ + (size_t)c * C_) * H_ + h) * D_;
    const int    r0   = 4 * w + 2 * h16;   // first of this lane's two rows
    const size_t rowg = base + (size_t)r0 * RS + 4 * l16;

    // ---- k,q loads up front (4 LDG.128s in flight) ----
    const float4 k0 = *(const float4*)(k + rowg);
    const float4 k1 = *(const float4*)(k + rowg + RS);
    const float4 q0 = *(const float4*)(q + rowg);
    const float4 q1 = *(const float4*)(q + rowg + RS);

    // ---- carry partials: 4-way chunk split over up to c priors (L2 loads) ----
    {
        const int d = tid & 63, p = tid >> 6;
        const int lo = p * 16;
        const int hi = (c < lo + 16) ? c : (lo + 16);
        float run = 0.0f;
        const float* cs = &g_chunksum[(bh << 6) * D_ + d];
        #pragma unroll 4
        for (int cc = lo; cc < hi; cc++) run += cs[cc * D_];
        carp[p * 64 + d] = run;
    }

    // ---- feature maps + pair column sums + cross-half exchange ----
    const float4 kf0 = fmap4(k0);
    const float4 kf1 = fmap4(k1);
    const float4 qf0 = fmap4(q0);
    const float4 qf1 = fmap4(q1);

    const float4 cs2 = add4(kf0, kf1);     // this half's 2-row column sums
    float4 other;                          // the other half's cs2
    other.x = __shfl_xor_sync(0xFFFFFFFFu, cs2.x, 16);
    other.y = __shfl_xor_sync(0xFFFFFFFFu, cs2.y, 16);
    other.z = __shfl_xor_sync(0xFFFFFFFFu, cs2.z, 16);
    other.w = __shfl_xor_sync(0xFFFFFFFFu, cs2.w, 16);

    if (h16 == 0) wsum[w][l16] = add4(cs2, other);   // 4-row warp total
    __syncthreads();                       // the ONLY block barrier

    // ---- v loads: issue now, consumed at the end (covered by compute) ----
    const float4 v0 = *(const float4*)(v + rowg);
    const float4 v1 = *(const float4*)(v + rowg + RS);

    // ---- running base for this lane's d-group: chunk carry + prior warps ----
    float4 runb;
    {
        const float4* cp = (const float4*)carp;      // [4][16] float4
        runb = add4(add4(cp[l16], cp[16 + l16]), add4(cp[32 + l16], cp[48 + l16]));
    }
    for (int ww = 0; ww < w; ww++) runb = add4(runb, wsum[ww][l16]);
    if (h16) runb = add4(runb, other);     // half 1 also sums rows {4w, 4w+1}

    // ---- time-cumsums and denominators ----
    const float4 cum0 = add4(runb, kf0);
    float den0 = dot4(qf0, cum0);
    const float4 cum1 = add4(cum0, kf1);
    float den1 = dot4(qf1, cum1);

    // ---- numerators: within-row d-cumsum (4-step width-16 scan each) ----
    float S0, S1;
    {
        const float g0 = kf0.x + kf0.y + kf0.z + kf0.w;
        float incl = g0;
        #pragma unroll
        for (int o = 1; o < 16; o <<= 1) {
            const float n = __shfl_up_sync(0xFFFFFFFFu, incl, o, 16);
            if (l16 >= o) incl += n;
        }
        float a = (incl - g0) + kf0.x;  S0  = qf0.x * a;
        a += kf0.y;                     S0 += qf0.y * a;
        a += kf0.z;                     S0 += qf0.z * a;
        a += kf0.w;                     S0 += qf0.w * a;
    }
    {
        const float g1 = kf1.x + kf1.y + kf1.z + kf1.w;
        float incl = g1;
        #pragma unroll
        for (int o = 1; o < 16; o <<= 1) {
            const float n = __shfl_up_sync(0xFFFFFFFFu, incl, o, 16);
            if (l16 >= o) incl += n;
        }
        float a = (incl - g1) + kf1.x;  S1  = qf1.x * a;
        a += kf1.y;                     S1 += qf1.y * a;
        a += kf1.z;                     S1 += qf1.z * a;
        a += kf1.w;                     S1 += qf1.w * a;
    }

    // ---- width-16 butterfly reductions (both halves ride the same steps) ----
    #pragma unroll
    for (int o = 8; o > 0; o >>= 1) {
        S0   += __shfl_xor_sync(0xFFFFFFFFu, S0, o);
        den0 += __shfl_xor_sync(0xFFFFFFFFu, den0, o);
        S1   += __shfl_xor_sync(0xFFFFFFFFu, S1, o);
        den1 += __shfl_xor_sync(0xFFFFFFFFu, den1, o);
    }

    // ---- scale and store ----
    const float sc0 = __fdividef(S0, den0);
    const float sc1 = __fdividef(S1, den1);
    float4 o0 = v0, o1 = v1;
    o0.x *= sc0; o0.y *= sc0; o0.z *= sc0; o0.w *= sc0;
    o1.x *= sc1; o1.y *= sc1; o1.z *= sc1; o1.w *= sc1;
    *(float4*)(out + rowg)      = o0;
    *(float4*)(out + rowg + RS) = o1;
}

extern "C" void kernel_launch(void* const* d_in, const int* in_sizes, int n_in,
                              void* d_out, int out_size) {
    const float* q = (const float*)d_in[0];
    const float* k = (const float*)d_in[1];
    const float* v = (const float*)d_in[2];
    float* out = (float*)d_out;

    const int nblocks = B_ * H_ * NC_;     // 1024
    k_chunksum<<<nblocks, 256>>>(k);
    k_main<<<nblocks, 256>>>(q, k, v, out);
}